// round 15
// baseline (speedup 1.0000x reference)
#include <cuda_runtime.h>
#include <math.h>

// ChannelAttention — R15: fused, fire-and-forget arrivals + static election.
// x  : [B=8, O=8, S=32, C=64, 32, 32] fp32 (512 MB streamed once)
// w1 : [8,64,64], w2 : [8,64,64] fp32
// out: [B,O,S,C] fp32
//
// Grid = 16384 CTAs x 256 thr (8 warps = 8 channel rows; 8 CTAs per blk).
// Group = 8 blks = 64 CTAs. CTAs with (bx&63)!=63: pool, fence+red (no
// return), exit — minimal slot-idle. CTA bx&63==63: pools, stages weights
// while spinning on acquire-load of the counter (63 arrivals), resets it,
// then runs warp-per-blk MLP for the 8 blks (warp w -> blk grp*8+w).

#define C_DIM   64
#define HW_DIM  1024
#define O_DIM   8
#define S_DIM   32
#define NBLK    2048            // B*O*S
#define NGRP    256             // 8-blk groups
#define FULLM   0xFFFFFFFFu

__device__ float2       g_pool[NBLK * C_DIM];
__device__ unsigned int g_cnt[NGRP];   // zero-init; designated CTA resets

__global__ __launch_bounds__(256, 6)
void fused_kernel(const float* __restrict__ x,
                  const float* __restrict__ w1,
                  const float* __restrict__ w2,
                  float* __restrict__ out)
{
    __shared__ float t1[C_DIM * 65];   // transposed w1
    __shared__ float t2[C_DIM * 65];   // transposed w2

    const int tid  = threadIdx.x;
    const int lane = tid & 31;
    const int wid  = tid >> 5;                 // 8 warps
    const int bx   = blockIdx.x;
    const int gw   = bx * 8 + wid;             // row id = blk*64 + c
    const int grp  = bx >> 6;                  // 64 CTAs per 8-blk group

    // ---------------- pooling: one warp per channel row ----------------
    const float4* row = reinterpret_cast<const float4*>(x)
                      + (size_t)gw * (HW_DIM / 4) + lane;

    float4 v0 = __ldcs(row + 0 * 32);
    float4 v1 = __ldcs(row + 1 * 32);
    float4 v2 = __ldcs(row + 2 * 32);
    float4 v3 = __ldcs(row + 3 * 32);
    float4 v4 = __ldcs(row + 4 * 32);
    float4 v5 = __ldcs(row + 5 * 32);
    float4 v6 = __ldcs(row + 6 * 32);
    float4 v7 = __ldcs(row + 7 * 32);

    float sa = (v0.x + v0.y) + (v0.z + v0.w);
    float sb = (v1.x + v1.y) + (v1.z + v1.w);
    float sc = (v2.x + v2.y) + (v2.z + v2.w);
    float sd = (v3.x + v3.y) + (v3.z + v3.w);
    sa += (v4.x + v4.y) + (v4.z + v4.w);
    sb += (v5.x + v5.y) + (v5.z + v5.w);
    sc += (v6.x + v6.y) + (v6.z + v6.w);
    sd += (v7.x + v7.y) + (v7.z + v7.w);

    float ma = fmaxf(fmaxf(v0.x, v0.y), fmaxf(v0.z, v0.w));
    float mb = fmaxf(fmaxf(v1.x, v1.y), fmaxf(v1.z, v1.w));
    float mc = fmaxf(fmaxf(v2.x, v2.y), fmaxf(v2.z, v2.w));
    float md = fmaxf(fmaxf(v3.x, v3.y), fmaxf(v3.z, v3.w));
    ma = fmaxf(ma, fmaxf(fmaxf(v4.x, v4.y), fmaxf(v4.z, v4.w)));
    mb = fmaxf(mb, fmaxf(fmaxf(v5.x, v5.y), fmaxf(v5.z, v5.w)));
    mc = fmaxf(mc, fmaxf(fmaxf(v6.x, v6.y), fmaxf(v6.z, v6.w)));
    md = fmaxf(md, fmaxf(fmaxf(v7.x, v7.y), fmaxf(v7.z, v7.w)));

    float s = (sa + sb) + (sc + sd);
    float m = fmaxf(fmaxf(ma, mb), fmaxf(mc, md));

    #pragma unroll
    for (int off = 16; off > 0; off >>= 1) {
        s += __shfl_xor_sync(FULLM, s, off);
        m = fmaxf(m, __shfl_xor_sync(FULLM, m, off));
    }
    if (lane == 0)
        g_pool[gw] = make_float2(s * (1.0f / (float)HW_DIM), m);
    __syncthreads();                           // all warps' pooled stores issued

    if ((bx & 63) != 63) {
        // -------- non-designated: fire-and-forget arrival, exit --------
        if (tid == 0) {
            __threadfence();                   // release pooled writes
            unsigned int* cnt = &g_cnt[grp];
            asm volatile("red.release.gpu.global.add.u32 [%0], 1;"
                         :: "l"(cnt) : "memory");
        }
        return;
    }

    // ================= designated CTA: MLP tail for 8 blks =================
    const int blk0 = grp * 8;
    const int o    = (grp >> 2) & 7;           // (blk0/32)%8
    const int w    = tid >> 5;                 // warp = blk within group

    // stage weights transposed WHILE peers drain (independent of counter)
    const float* s1 = w1 + (size_t)o * C_DIM * C_DIM;
    const float* s2 = w2 + (size_t)o * C_DIM * C_DIM;
    #pragma unroll
    for (int i = 0; i < 16; ++i) {
        int idx = tid + i * 256;               // = n*64 + c
        int n = idx >> 6, c = idx & 63;
        t1[c * 65 + n] = __ldg(s1 + idx);
        t2[c * 65 + n] = __ldg(s2 + idx);
    }

    // wait for the 63 peer arrivals (acquire), then reset for replay
    if (tid == 0) {
        unsigned int v;
        unsigned int* cnt = &g_cnt[grp];
        do {
            asm volatile("ld.acquire.gpu.global.u32 %0, [%1];"
                         : "=r"(v) : "l"(cnt) : "memory");
            if (v < 63u) __nanosleep(64);
        } while (v < 63u);
        *cnt = 0u;
    }
    __syncthreads();                           // weights staged + data visible

    const int blk = blk0 + w;
    float2 pa = __ldcg(&g_pool[blk * C_DIM + lane]);
    float2 pb = __ldcg(&g_pool[blk * C_DIM + 32 + lane]);
    const float pml = pa.x, pxl = pa.y;
    const float pmh = pb.x, pxh = pb.y;

    // FC1: lane computes hidden n0=lane, n1=lane+32
    float am0 = 0.f, ax0 = 0.f, am1 = 0.f, ax1 = 0.f;
    #pragma unroll 8
    for (int c = 0; c < 32; ++c) {
        float pmc = __shfl_sync(FULLM, pml, c);
        float pxc = __shfl_sync(FULLM, pxl, c);
        float wl  = t1[c * 65 + lane];
        float wh  = t1[c * 65 + 32 + lane];
        am0 = fmaf(pmc, wl, am0); ax0 = fmaf(pxc, wl, ax0);
        am1 = fmaf(pmc, wh, am1); ax1 = fmaf(pxc, wh, ax1);
    }
    #pragma unroll 8
    for (int c = 32; c < 64; ++c) {
        float pmc = __shfl_sync(FULLM, pmh, c - 32);
        float pxc = __shfl_sync(FULLM, pxh, c - 32);
        float wl  = t1[c * 65 + lane];
        float wh  = t1[c * 65 + 32 + lane];
        am0 = fmaf(pmc, wl, am0); ax0 = fmaf(pxc, wl, ax0);
        am1 = fmaf(pmc, wh, am1); ax1 = fmaf(pxc, wh, ax1);
    }
    const float hl = fmaxf(am0, 0.f) + fmaxf(ax0, 0.f);   // h[lane]
    const float hh = fmaxf(am1, 0.f) + fmaxf(ax1, 0.f);   // h[lane+32]

    // FC2 + sigmoid (FC2 linear => single pass over summed hidden)
    float a0 = 0.f, a1 = 0.f;
    #pragma unroll 8
    for (int h = 0; h < 32; ++h) {
        float hc = __shfl_sync(FULLM, hl, h);
        float wl = t2[h * 65 + lane];
        float wh = t2[h * 65 + 32 + lane];
        a0 = fmaf(hc, wl, a0); a1 = fmaf(hc, wh, a1);
    }
    #pragma unroll 8
    for (int h = 32; h < 64; ++h) {
        float hc = __shfl_sync(FULLM, hh, h - 32);
        float wl = t2[h * 65 + lane];
        float wh = t2[h * 65 + 32 + lane];
        a0 = fmaf(hc, wl, a0); a1 = fmaf(hc, wh, a1);
    }

    out[(size_t)blk * C_DIM + lane]      = 1.0f / (1.0f + __expf(-a0));
    out[(size_t)blk * C_DIM + 32 + lane] = 1.0f / (1.0f + __expf(-a1));
}

extern "C" void kernel_launch(void* const* d_in, const int* in_sizes, int n_in,
                              void* d_out, int out_size)
{
    const float* x  = (const float*)d_in[0];
    const float* w1 = (const float*)d_in[1];
    const float* w2 = (const float*)d_in[2];
    float* out = (float*)d_out;

    fused_kernel<<<NBLK * 8, 256>>>(x, w1, w2, out);
}

// round 16
// speedup vs baseline: 1.1180x; 1.1180x over previous
#include <cuda_runtime.h>
#include <math.h>

// ChannelAttention — R16: split + PDL with trigger at END of pool CTAs.
//   pool_kernel : byte-identical streaming pool (73.5us, ~7TB/s, HBM wall);
//                 cudaTriggerProgrammaticLaunchCompletion() AFTER the store,
//                 so the mlp grid launches only during the drain wave.
//   mlp_kernel  : stages weights (pool-independent) BEFORE
//                 cudaGridDependencySynchronize(); post-sync = L2-hit pooled
//                 loads + warp-local FC1/FC2.
// x  : [B=8, O=8, S=32, C=64, 32, 32] fp32 (512 MB)
// w1 : [8,64,64], w2 : [8,64,64] fp32
// out: [B,O,S,C] fp32

#define C_DIM   64
#define HW_DIM  1024
#define O_DIM   8
#define S_DIM   32
#define NBLK    2048            // B*O*S
#define FULLM   0xFFFFFFFFu

__device__ float2 g_pool[NBLK * C_DIM];

// ---------------- Kernel A: pooling (R4 exact; trigger at END) ----------------
__global__ __launch_bounds__(256, 6)
void pool_kernel(const float* __restrict__ x)
{
    const int lane = threadIdx.x & 31;
    const int gw   = blockIdx.x * 8 + (threadIdx.x >> 5);  // row = (blk, c)
    const float4* row = reinterpret_cast<const float4*>(x) + (size_t)gw * (HW_DIM / 4) + lane;

    float4 v0 = __ldcs(row + 0 * 32);
    float4 v1 = __ldcs(row + 1 * 32);
    float4 v2 = __ldcs(row + 2 * 32);
    float4 v3 = __ldcs(row + 3 * 32);
    float4 v4 = __ldcs(row + 4 * 32);
    float4 v5 = __ldcs(row + 5 * 32);
    float4 v6 = __ldcs(row + 6 * 32);
    float4 v7 = __ldcs(row + 7 * 32);

    float sa = (v0.x + v0.y) + (v0.z + v0.w);
    float sb = (v1.x + v1.y) + (v1.z + v1.w);
    float sc = (v2.x + v2.y) + (v2.z + v2.w);
    float sd = (v3.x + v3.y) + (v3.z + v3.w);
    sa += (v4.x + v4.y) + (v4.z + v4.w);
    sb += (v5.x + v5.y) + (v5.z + v5.w);
    sc += (v6.x + v6.y) + (v6.z + v6.w);
    sd += (v7.x + v7.y) + (v7.z + v7.w);

    float ma = fmaxf(fmaxf(v0.x, v0.y), fmaxf(v0.z, v0.w));
    float mb = fmaxf(fmaxf(v1.x, v1.y), fmaxf(v1.z, v1.w));
    float mc = fmaxf(fmaxf(v2.x, v2.y), fmaxf(v2.z, v2.w));
    float md = fmaxf(fmaxf(v3.x, v3.y), fmaxf(v3.z, v3.w));
    ma = fmaxf(ma, fmaxf(fmaxf(v4.x, v4.y), fmaxf(v4.z, v4.w)));
    mb = fmaxf(mb, fmaxf(fmaxf(v5.x, v5.y), fmaxf(v5.z, v5.w)));
    mc = fmaxf(mc, fmaxf(fmaxf(v6.x, v6.y), fmaxf(v6.z, v6.w)));
    md = fmaxf(md, fmaxf(fmaxf(v7.x, v7.y), fmaxf(v7.z, v7.w)));

    float s = (sa + sb) + (sc + sd);
    float m = fmaxf(fmaxf(ma, mb), fmaxf(mc, md));

    #pragma unroll
    for (int off = 16; off > 0; off >>= 1) {
        s += __shfl_xor_sync(FULLM, s, off);
        m = fmaxf(m, __shfl_xor_sync(FULLM, m, off));
    }
    if (lane == 0)
        g_pool[gw] = make_float2(s * (1.0f / (float)HW_DIM), m);

    // signal AFTER the work: secondary grid launches during the drain wave
    cudaTriggerProgrammaticLaunchCompletion();
}

// ---------------- Kernel B: warp-per-blk MLP, PDL-overlapped prologue --------
// grid = 256 CTAs x 256 thr. CTA = 8 warps = 8 consecutive blks (same o).
__global__ __launch_bounds__(256)
void mlp_kernel(const float* __restrict__ w1,
                const float* __restrict__ w2,
                float* __restrict__ out)
{
    __shared__ float t1[C_DIM * 65];
    __shared__ float t2[C_DIM * 65];

    const int tid  = threadIdx.x;
    const int lane = tid & 31;
    const int w    = tid >> 5;                 // warp = blk within CTA
    const int blk0 = blockIdx.x * 8;
    const int o    = (blk0 / S_DIM) % O_DIM;   // same for all 8 warps

    // ---- prologue (overlaps pool drain): stage weights transposed ----
    const float* s1 = w1 + (size_t)o * C_DIM * C_DIM;
    const float* s2 = w2 + (size_t)o * C_DIM * C_DIM;
    #pragma unroll
    for (int i = 0; i < 16; ++i) {
        int idx = tid + i * 256;               // = n*64 + c
        int n = idx >> 6, c = idx & 63;
        t1[c * 65 + n] = __ldg(s1 + idx);
        t2[c * 65 + n] = __ldg(s2 + idx);
    }
    __syncthreads();

    // ---- wait for pool completion + memory visibility ----
    cudaGridDependencySynchronize();

    const int blk = blk0 + w;
    float2 pa = g_pool[blk * C_DIM + lane];        // L2-fresh
    float2 pb = g_pool[blk * C_DIM + 32 + lane];
    const float pml = pa.x, pxl = pa.y;
    const float pmh = pb.x, pxh = pb.y;

    // FC1: lane computes hidden n0=lane, n1=lane+32
    float am0 = 0.f, ax0 = 0.f, am1 = 0.f, ax1 = 0.f;
    #pragma unroll 8
    for (int c = 0; c < 32; ++c) {
        float pmc = __shfl_sync(FULLM, pml, c);
        float pxc = __shfl_sync(FULLM, pxl, c);
        float wl  = t1[c * 65 + lane];
        float wh  = t1[c * 65 + 32 + lane];
        am0 = fmaf(pmc, wl, am0); ax0 = fmaf(pxc, wl, ax0);
        am1 = fmaf(pmc, wh, am1); ax1 = fmaf(pxc, wh, ax1);
    }
    #pragma unroll 8
    for (int c = 32; c < 64; ++c) {
        float pmc = __shfl_sync(FULLM, pmh, c - 32);
        float pxc = __shfl_sync(FULLM, pxh, c - 32);
        float wl  = t1[c * 65 + lane];
        float wh  = t1[c * 65 + 32 + lane];
        am0 = fmaf(pmc, wl, am0); ax0 = fmaf(pxc, wl, ax0);
        am1 = fmaf(pmc, wh, am1); ax1 = fmaf(pxc, wh, ax1);
    }
    const float hl = fmaxf(am0, 0.f) + fmaxf(ax0, 0.f);   // h[lane]
    const float hh = fmaxf(am1, 0.f) + fmaxf(ax1, 0.f);   // h[lane+32]

    // FC2 + sigmoid (FC2 linear => single pass over summed hidden)
    float a0 = 0.f, a1 = 0.f;
    #pragma unroll 8
    for (int h = 0; h < 32; ++h) {
        float hc = __shfl_sync(FULLM, hl, h);
        float wl = t2[h * 65 + lane];
        float wh = t2[h * 65 + 32 + lane];
        a0 = fmaf(hc, wl, a0); a1 = fmaf(hc, wh, a1);
    }
    #pragma unroll 8
    for (int h = 32; h < 64; ++h) {
        float hc = __shfl_sync(FULLM, hh, h - 32);
        float wl = t2[h * 65 + lane];
        float wh = t2[h * 65 + 32 + lane];
        a0 = fmaf(hc, wl, a0); a1 = fmaf(hc, wh, a1);
    }

    out[(size_t)blk * C_DIM + lane]      = 1.0f / (1.0f + __expf(-a0));
    out[(size_t)blk * C_DIM + 32 + lane] = 1.0f / (1.0f + __expf(-a1));
}

extern "C" void kernel_launch(void* const* d_in, const int* in_sizes, int n_in,
                              void* d_out, int out_size)
{
    const float* x  = (const float*)d_in[0];
    const float* w1 = (const float*)d_in[1];
    const float* w2 = (const float*)d_in[2];
    float* out = (float*)d_out;

    pool_kernel<<<NBLK * 8, 256>>>(x);

    // PDL: mlp grid comes up during pool's drain; it synchronizes internally.
    cudaLaunchConfig_t cfg = {};
    cfg.gridDim  = dim3(NBLK / 8);
    cfg.blockDim = dim3(256);
    cfg.dynamicSmemBytes = 0;
    cfg.stream = 0;
    cudaLaunchAttribute attrs[1];
    attrs[0].id = cudaLaunchAttributeProgrammaticStreamSerialization;
    attrs[0].val.programmaticStreamSerializationAllowed = 1;
    cfg.attrs = attrs;
    cfg.numAttrs = 1;
    cudaLaunchKernelEx(&cfg, mlp_kernel, w1, w2, out);
}